// round 16
// baseline (speedup 1.0000x reference)
#include <cuda_runtime.h>
#include <cstdint>

// ---------------------------------------------------------------------------
// SubsetOperator: output = one-hot(top_k(scores)) in fp32.
// Reference forward reduces exactly to this (non-selected lanes exactly 0.0f,
// selected 1.0f within ~2 ulp; top_k(khot)==top_k(scores), boundary margin
// ~6.5e-3 >> all perturbations).
//
// R15: ONE kernel, 513 blocks. Blocks [0,512) = streaming workers (zero-fill
// + maxima + inline candidate collection, as R13). Block 512 = selector: it
// spins on an arrival counter (threadFenceReduction idiom) and the instant
// the last worker arrives it ranks the ~150 candidates and writes the 1.0f
// outputs. Removes the second kernel's ~5-6us launch/ramp floor entirely.
// ---------------------------------------------------------------------------

#define SEG_ELEMS    2048
#define SEG_F4       (SEG_ELEMS / 4)
#define SUB_F4       64                 // 256 elems per sub-segment
#define SUBS_PER_SEG 8
#define MAX_SEGS     8192
#define MAX_SUB      (MAX_SEGS * SUBS_PER_SEG)
#define MAX_BLKA     512
#define MAXK         1024
#define TPB          512
#define WARPS_A      (TPB / 32)
#define SEGL_CAP     1024
#define SUBL_CAP     1536
#define CKEY_CAP     2048
#define CAND_CAP     65536

__device__ unsigned int       g_seg_max[MAX_SEGS];
__device__ unsigned int       g_sub_max[MAX_SUB];
__device__ unsigned int       g_blk_max[MAX_BLKA];
__device__ unsigned long long g_cand[CAND_CAP];
__device__ int                g_cand_count;   // zero-init; selector resets
__device__ unsigned int       g_done;         // zero-init; selector resets

// monotone mapping: fp32 total order -> uint32 order
__device__ __forceinline__ unsigned int fmono(float x) {
    unsigned int b = __float_as_uint(x);
    return b ^ ((unsigned int)((int)b >> 31) | 0x80000000u);
}

__device__ __forceinline__ void append_cand(unsigned int u, int idx) {
    int p = atomicAdd(&g_cand_count, 1);
    if (p < CAND_CAP)
        g_cand[p] = ((unsigned long long)u << 32) |
                    (unsigned int)(0xFFFFFFFFu - (unsigned int)idx);
}

// warp-0 radix step for the fallback path
__device__ __forceinline__ void radix_pick(const unsigned int* hist,
                                           unsigned int* s_prefix, int* s_rem,
                                           int shift, int lane) {
    unsigned int b[8];
    int base = lane * 8;
    unsigned int tot = 0u;
#pragma unroll
    for (int e = 0; e < 8; ++e) { b[e] = hist[base + e]; tot += b[e]; }
    unsigned int acc = tot;
#pragma unroll
    for (int off = 1; off < 32; off <<= 1) {
        unsigned int o = __shfl_down_sync(0xFFFFFFFFu, acc, off);
        if (lane + off < 32) acc += o;
    }
    unsigned int run = acc - tot;
    int rem = *s_rem;
    unsigned int pref = *s_prefix;
#pragma unroll
    for (int e = 7; e >= 0; --e) {
        unsigned int ge = run + b[e];
        if ((int)run < rem && (int)ge >= rem) {
            *s_prefix = pref | ((unsigned int)(base + e) << shift);
            *s_rem = rem - (int)run;
        }
        run = ge;
    }
}

// ---------------------------------------------------------------------------
__global__ void __launch_bounds__(TPB, 2)
kAll(const float* __restrict__ scores, float* __restrict__ out,
     const int* kptr, int n, int nSeg, int nWork, int nBlkA) {
    __shared__ unsigned int wmax[WARPS_A];
    __shared__ unsigned long long ckeys[CKEY_CAP];
    __shared__ unsigned int hist[256];
    __shared__ unsigned int s_prefix;
    __shared__ int s_rem;
    __shared__ int seglist[SEGL_CAP];
    __shared__ int sublist[SUBL_CAP];
    __shared__ int s_nseg, s_nsub, s_nc;

    int tid  = threadIdx.x;
    int lane = tid & 31;

    if ((int)blockIdx.x < nWork) {
        // =================== WORKER PATH (streaming pass) ===================
        int warp = tid >> 5;
        int seg  = blockIdx.x * WARPS_A + warp;
        const unsigned int T0 = fmono(4.3f);   // conservative candidate floor

        unsigned int m = 0u;
        if (seg < nSeg) {
            const float4* s4 = (const float4*)scores;
            float4*       o4 = (float4*)out;
            int base4 = seg * SEG_F4;
            float4 z = make_float4(0.f, 0.f, 0.f, 0.f);
            bool full = (base4 + SEG_F4) * 4 <= n;

            if (full) {
#pragma unroll
                for (int h = 0; h < 2; ++h) {          // 2 halves x 8 float4
                    int b4 = base4 + h * 256;
                    float4 v[8];
#pragma unroll
                    for (int j = 0; j < 8; ++j)        // batched loads: MLP=8
                        v[j] = __ldcs(s4 + b4 + j * 32 + lane);
#pragma unroll
                    for (int j = 0; j < 8; ++j)
                        __stcs(o4 + b4 + j * 32 + lane, z);
#pragma unroll
                    for (int j = 0; j < 8; j += 2) {   // 256-elem sub-segment
                        unsigned int u0 = fmono(v[j].x),   u1 = fmono(v[j].y);
                        unsigned int u2 = fmono(v[j].z),   u3 = fmono(v[j].w);
                        unsigned int u4 = fmono(v[j+1].x), u5 = fmono(v[j+1].y);
                        unsigned int u6 = fmono(v[j+1].z), u7 = fmono(v[j+1].w);
                        unsigned int a = u0 > u1 ? u0 : u1;
                        unsigned int b = u2 > u3 ? u2 : u3;
                        unsigned int d = u4 > u5 ? u4 : u5;
                        unsigned int e = u6 > u7 ? u6 : u7;
                        unsigned int ab = a > b ? a : b;
                        unsigned int de = d > e ? d : e;
                        unsigned int c  = ab > de ? ab : de;
                        if (c >= T0) {                 // rare: append cands
                            int i0 = (b4 + j * 32 + lane) * 4;
                            int i1 = (b4 + (j + 1) * 32 + lane) * 4;
                            if (u0 >= T0) append_cand(u0, i0);
                            if (u1 >= T0) append_cand(u1, i0 + 1);
                            if (u2 >= T0) append_cand(u2, i0 + 2);
                            if (u3 >= T0) append_cand(u3, i0 + 3);
                            if (u4 >= T0) append_cand(u4, i1);
                            if (u5 >= T0) append_cand(u5, i1 + 1);
                            if (u6 >= T0) append_cand(u6, i1 + 2);
                            if (u7 >= T0) append_cand(u7, i1 + 3);
                        }
                        unsigned int t = c;            // warp submax reduce
#pragma unroll
                        for (int off = 16; off > 0; off >>= 1) {
                            unsigned int o = __shfl_xor_sync(0xFFFFFFFFu, t, off);
                            if (o > t) t = o;
                        }
                        if (lane == 0)
                            g_sub_max[seg * SUBS_PER_SEG + h * 4 + (j >> 1)] = t;
                        if (t > m) m = t;
                    }
                }
            } else {                                   // generic tail segment
                unsigned int m2 = 0u;
                for (int j = 0; j < SEG_F4 / 32; ++j) {
                    int idx4 = base4 + j * 32 + lane;
                    unsigned int c = 0u;
                    for (int e = 0; e < 4; ++e) {
                        int i = idx4 * 4 + e;
                        if (i < n) {
                            unsigned int uu = fmono(scores[i]);
                            if (uu > c) c = uu;
                            if (uu >= T0) append_cand(uu, i);
                            out[i] = 0.f;
                        }
                    }
                    if (c > m2) m2 = c;
                    if (j & 1) {
                        unsigned int t = m2;
                        for (int off = 16; off > 0; off >>= 1) {
                            unsigned int o = __shfl_xor_sync(0xFFFFFFFFu, t, off);
                            if (o > t) t = o;
                        }
                        if (lane == 0)
                            g_sub_max[seg * SUBS_PER_SEG + (j >> 1)] = t;
                        if (t > m) m = t;
                        m2 = 0u;
                    }
                }
            }
            if (lane == 0) g_seg_max[seg] = m;
        }
        if (lane == 0) wmax[tid >> 5] = m;
        __syncthreads();
        if ((tid >> 5) == 0) {
            unsigned int v = (lane < WARPS_A) ? wmax[lane] : 0u;
#pragma unroll
            for (int off = 8; off > 0; off >>= 1) {
                unsigned int o = __shfl_xor_sync(0xFFFFFFFFu, v, off);
                if (o > v) v = o;
            }
            if (lane == 0) g_blk_max[blockIdx.x] = v;
        }
        // threadFenceReduction idiom: make this block's writes visible, then
        // signal arrival. Selector consumes only after observing all arrivals.
        __threadfence();
        __syncthreads();
        if (tid == 0) atomicAdd(&g_done, 1u);
        return;
    }

    // ====================== SELECTOR PATH (1 block) ======================
    // prologue (independent of workers)
    int k = kptr ? *kptr : 32;
    if (k < 1) k = 1;
    if (k > MAXK) k = MAXK;
    if (tid < 256) hist[tid] = 0u;
    if (tid == 0) { s_prefix = 0u; s_rem = k; s_nseg = 0; s_nsub = 0; s_nc = 0; }
    __syncthreads();

    // spin until all workers have arrived (L2 atomic poll, ~resident warm SM)
    if (tid == 0) {
        while (atomicAdd(&g_done, 0u) < (unsigned int)nWork) __nanosleep(64);
    }
    __syncthreads();
    __threadfence();          // acquire: order subsequent reads after poll

    int C0 = g_cand_count;

    if (C0 >= k && C0 <= CKEY_CAP) {
        // ---- FAST PATH: C0 >= k proves candidates contain the top-k ----
        for (int j = tid; j < C0; j += TPB) ckeys[j] = g_cand[j];
        __syncthreads();
        for (int j = tid; j < C0; j += TPB) {
            unsigned long long kj = ckeys[j];
            int rank = 0;
            for (int i = 0; i < C0; ++i) rank += (ckeys[i] > kj);
            if (rank < k)
                out[0xFFFFFFFFu - (unsigned int)(kj & 0xFFFFFFFFu)] = 1.0f;
        }
        __syncthreads();
        if (tid == 0) { g_cand_count = 0; g_done = 0; }   // reset for replay
        return;
    }

    // ---- FALLBACK: full drill-down (any input shape) ----
    const unsigned int* src = (k <= nBlkA) ? g_blk_max : g_seg_max;
    int M = (k <= nBlkA) ? nBlkA : nSeg;
    if (k > M) k = M;

    for (int j = tid; j < M; j += TPB) atomicAdd(&hist[src[j] >> 24], 1u);
    __syncthreads();
    if (tid < 32) radix_pick(hist, &s_prefix, &s_rem, 24, lane);
    __syncthreads();
    if (tid < 256) hist[tid] = 0u;
    unsigned int p8 = s_prefix >> 24;
    __syncthreads();
    for (int j = tid; j < M; j += TPB) {
        unsigned int v = src[j];
        if ((v >> 24) == p8) atomicAdd(&hist[(v >> 16) & 255u], 1u);
    }
    __syncthreads();
    if (tid < 32) radix_pick(hist, &s_prefix, &s_rem, 16, lane);
    __syncthreads();
    unsigned int T = s_prefix;     // 16-bit floor <= true k-th max

    int nSeg4 = nSeg >> 2;
    const uint4* sm4 = (const uint4*)g_seg_max;
    for (int j = tid; j < nSeg4; j += TPB) {
        uint4 v = sm4[j];
        int b = 4 * j;
        if (v.x >= T) { int p = atomicAdd(&s_nseg, 1); if (p < SEGL_CAP) seglist[p] = b;     }
        if (v.y >= T) { int p = atomicAdd(&s_nseg, 1); if (p < SEGL_CAP) seglist[p] = b + 1; }
        if (v.z >= T) { int p = atomicAdd(&s_nseg, 1); if (p < SEGL_CAP) seglist[p] = b + 2; }
        if (v.w >= T) { int p = atomicAdd(&s_nseg, 1); if (p < SEGL_CAP) seglist[p] = b + 3; }
    }
    for (int j = nSeg4 * 4 + tid; j < nSeg; j += TPB) {
        if (g_seg_max[j] >= T) {
            int p = atomicAdd(&s_nseg, 1);
            if (p < SEGL_CAP) seglist[p] = j;
        }
    }
    __syncthreads();
    int F = s_nseg < SEGL_CAP ? s_nseg : SEGL_CAP;

    for (int t = tid; t < F * SUBS_PER_SEG; t += TPB) {
        int sub = seglist[t >> 3] * SUBS_PER_SEG + (t & 7);
        if (g_sub_max[sub] >= T) {
            int p = atomicAdd(&s_nsub, 1);
            if (p < SUBL_CAP) sublist[p] = sub;
        }
    }
    __syncthreads();
    int F2 = s_nsub < SUBL_CAP ? s_nsub : SUBL_CAP;

    const float4* s4 = (const float4*)scores;
    int W = F2 * SUB_F4;
    for (int w = tid; w < W; w += TPB) {
        int idx4 = sublist[w >> 6] * SUB_F4 + (w & 63);
        int e0   = idx4 * 4;
        if (e0 + 3 < n) {
            float4 v = s4[idx4];
            unsigned int uu[4] = {fmono(v.x), fmono(v.y), fmono(v.z), fmono(v.w)};
#pragma unroll
            for (int e = 0; e < 4; ++e) {
                if (uu[e] >= T) {
                    int p = atomicAdd(&s_nc, 1);
                    if (p < CKEY_CAP)
                        ckeys[p] = ((unsigned long long)uu[e] << 32) |
                                   (unsigned int)(0xFFFFFFFFu - (unsigned int)(e0 + e));
                }
            }
        } else {
            for (int e = 0; e < 4; ++e) {
                int i = e0 + e;
                if (i < n) {
                    unsigned int uu = fmono(scores[i]);
                    if (uu >= T) {
                        int p = atomicAdd(&s_nc, 1);
                        if (p < CKEY_CAP)
                            ckeys[p] = ((unsigned long long)uu << 32) |
                                       (unsigned int)(0xFFFFFFFFu - (unsigned int)i);
                    }
                }
            }
        }
    }
    __syncthreads();
    int C = s_nc < CKEY_CAP ? s_nc : CKEY_CAP;

    for (int j = tid; j < C; j += TPB) {
        unsigned long long kj = ckeys[j];
        int rank = 0;
        for (int i = 0; i < C; ++i) rank += (ckeys[i] > kj);
        if (rank < k)
            out[0xFFFFFFFFu - (unsigned int)(kj & 0xFFFFFFFFu)] = 1.0f;
    }
    __syncthreads();
    if (tid == 0) { g_cand_count = 0; g_done = 0; }       // reset for replay
}

// ---------------------------------------------------------------------------
extern "C" void kernel_launch(void* const* d_in, const int* in_sizes, int n_in,
                              void* d_out, int out_size) {
    const float* scores = (const float*)d_in[0];
    int n = in_sizes[0];
    const int* kptr = nullptr;
    for (int i = 0; i < n_in; ++i) {
        if (in_sizes[i] == 1) {
            kptr = (const int*)d_in[i];
        } else {
            scores = (const float*)d_in[i];
            n = in_sizes[i];
        }
    }
    float* out = (float*)d_out;

    int nSeg = (n + SEG_ELEMS - 1) / SEG_ELEMS;      // 8192 for N = 16,777,216
    if (nSeg > MAX_SEGS) nSeg = MAX_SEGS;
    int nWork = (nSeg + WARPS_A - 1) / WARPS_A;      // 512
    if (nWork > MAX_BLKA) nWork = MAX_BLKA;

    kAll<<<nWork + 1, TPB>>>(scores, out, kptr, n, nSeg, nWork, nWork);
}